// round 14
// baseline (speedup 1.0000x reference)
#include <cuda_runtime.h>
#include <cuda_bf16.h>
#include <cstdint>

#define DEVINL __device__ __forceinline__

static constexpr int CD = 1024;          // channel dim
static constexpr int BN = 4;             // batch
static constexpr int TNseq = 4096;       // seq len
static constexpr int MR = BN * TNseq;    // 16384 rows
static constexpr int NCH = 64;           // scan chunks
static constexpr int CHL = TNseq / NCH;  // 64 steps/chunk
static constexpr int N2 = 2048;          // QK8 row stride

// ------------------- scratch -------------------
static constexpr size_t MB  = 1024ull * 1024ull;
static constexpr size_t OFF_QK8  = 0;          // Q|K e4m3 [MR][2048]   32MB
static constexpr size_t OFF_E    = 32  * MB;   // E bf16 [MR][1024]     32MB
static constexpr size_t OFF_Y8   = 64  * MB;   // Y e4m3 [MR][1024]     16MB
static constexpr size_t OFF_H    = 80  * MB;   // h bf16                32MB
static constexpr size_t OFF_X8   = 112 * MB;   // x e4m3                16MB
static constexpr size_t OFF_G8   = 128 * MB;   // gate e4m3             16MB
static constexpr size_t OFF_OGB  = 144 * MB;   // (out*gate) bf16       32MB
static constexpr size_t OFF_WCAT = 176 * MB;   // Wcat bf16 [4096][1024] 8MB
static constexpr size_t OFF_WKT  = 184 * MB;   // Wk^T bf16 2MB
static constexpr size_t OFF_W0T  = 186 * MB;   // (W0+A@B)^T bf16 2MB
static constexpr size_t OFF_WG8  = 188 * MB;   // Wg e4m3*16 1MB
static constexpr size_t OFF_WOB  = 189 * MB;   // Wo bf16 2MB
static constexpr size_t OFF_CS   = 191 * MB;   // 1MB fp32 raw chunk sums
static constexpr size_t SCRATCH  = 192 * MB;
__device__ __align__(1024) unsigned char g_scratch[SCRATCH];

static constexpr float WSCALE = 16.0f;
static constexpr float INV_WSCALE = 1.0f / 16.0f;

// ------------------- helpers -------------------
DEVINL uint32_t s2u(const void* p) {
    uint32_t a;
    asm("{ .reg .u64 t; cvta.to.shared.u64 t, %1; cvt.u32.u64 %0, t; }" : "=r"(a) : "l"(p));
    return a;
}
DEVINL uint16_t f2e4m3x2(float lo, float hi) {
    uint16_t r;
    asm("cvt.rn.satfinite.e4m3x2.f32 %0, %1, %2;" : "=h"(r) : "f"(hi), "f"(lo));
    return r;
}
DEVINL uint32_t f4_to_e4m3x4(float a, float b, float c, float d) {
    uint32_t lo = f2e4m3x2(a, b);
    uint32_t hi = f2e4m3x2(c, d);
    return lo | (hi << 16);
}
DEVINL float e4m3_to_f(uint8_t b) {
    uint16_t s = (uint16_t)b;
    uint32_t h2;
    asm("cvt.rn.f16x2.e4m3x2 %0, %1;" : "=r"(h2) : "h"(s));
    __half h = *reinterpret_cast<__half*>(&h2);   // low half = low byte
    return __half2float(h);
}
#define SWZ128(x) ((x) ^ (((x) >> 3) & 0x70))
DEVINL void cpa16(uint32_t s, const void* g) {
    asm volatile("cp.async.cg.shared.global [%0], [%1], 16;" :: "r"(s), "l"(g));
}

// ------------------- fused prep: layernorm + all weight conversions -------------------
// grid: MR + 7*1024 blocks, 256 threads.
// blocks [0, MR): layernorm row (emit h bf16, x e4m3; block0 zeroes loss)
// blocks [MR, MR+7*1024): weight task m = (bid-MR)>>10, bx = (bid-MR)&1023
//   m=0: Wq*min(exp(loglr),1) -> Wcat[0:1024) bf16
//   m=1: Wk -> Wcat[1024:2048) bf16
//   m=2: Wv -> Wcat[2048:3072) bf16   (later WE = Wy0 - Wv overwrites, in gemm_we)
//   m=3: Wg*16 -> fp8
//   m=4: Wo -> bf16 WoB
//   m=5: WkT[d][c] = Wk[c][d] bf16
//   m=6: W0T[d][c] = W0[c][d] + sum_r A[c][r]*B[r][d] bf16
__global__ void __launch_bounds__(256) prep_all(
    const float* __restrict__ x, const float* __restrict__ lng, const float* __restrict__ lnb,
    __nv_bfloat16* __restrict__ hb, uint8_t* __restrict__ x8,
    const float* __restrict__ Wq, const float* __restrict__ Wk, const float* __restrict__ Wv,
    const float* __restrict__ Wg, const float* __restrict__ Wo, const float* __restrict__ W0,
    const float* __restrict__ Ai, const float* __restrict__ Bi, const float* __restrict__ loglr,
    __nv_bfloat16* __restrict__ Wcat, uint8_t* __restrict__ Og8, __nv_bfloat16* __restrict__ WoB,
    __nv_bfloat16* __restrict__ WkT, __nv_bfloat16* __restrict__ W0T,
    float* __restrict__ loss_slot) {
    int bid = blockIdx.x;
    int t = threadIdx.x;
    if (bid < MR) {
        int row = bid;
        if (row == 0 && t == 0) *loss_slot = 0.0f;
        const float4 v = ((const float4*)(x + (size_t)row * CD))[t];
        float s = v.x + v.y + v.z + v.w;
        float q = v.x * v.x + v.y * v.y + v.z * v.z + v.w * v.w;
#pragma unroll
        for (int o = 16; o > 0; o >>= 1) {
            s += __shfl_xor_sync(0xffffffffu, s, o);
            q += __shfl_xor_sync(0xffffffffu, q, o);
        }
        __shared__ float red[16];
        int wid = t >> 5;
        if ((t & 31) == 0) { red[wid] = s; red[8 + wid] = q; }
        __syncthreads();
        float ts = 0.f, tq = 0.f;
#pragma unroll
        for (int i = 0; i < 8; i++) { ts += red[i]; tq += red[8 + i]; }
        float mu = ts * (1.f / 1024.f);
        float var = tq * (1.f / 1024.f) - mu * mu;
        float rs = rsqrtf(var + 1e-5f);
        const float4 gv = ((const float4*)lng)[t];
        const float4 bv = ((const float4*)lnb)[t];
        float h0 = (v.x - mu) * rs * gv.x + bv.x;
        float h1 = (v.y - mu) * rs * gv.y + bv.y;
        float h2 = (v.z - mu) * rs * gv.z + bv.z;
        float h3 = (v.w - mu) * rs * gv.w + bv.w;
        __nv_bfloat162 ha = __floats2bfloat162_rn(h0, h1);
        __nv_bfloat162 hc = __floats2bfloat162_rn(h2, h3);
        uint2 hu; hu.x = *reinterpret_cast<uint32_t*>(&ha); hu.y = *reinterpret_cast<uint32_t*>(&hc);
        ((uint2*)(hb + (size_t)row * CD))[t] = hu;
        ((uint32_t*)(x8 + (size_t)row * CD))[t] = f4_to_e4m3x4(v.x, v.y, v.z, v.w);
        return;
    }
    int wb = bid - MR;
    int m = wb >> 10;
    int bx = wb & 1023;
    if (m < 3) {
        int i = bx * 256 + t;   // float4 index
        const float* W = (m == 0) ? Wq : (m == 1) ? Wk : Wv;
        float4 v = ((const float4*)W)[i];
        float s = 1.0f;
        if (m == 0) s = fminf(expf(loglr[i >> 8]), 1.0f);
        __nv_bfloat162 a = __floats2bfloat162_rn(v.x * s, v.y * s);
        __nv_bfloat162 b = __floats2bfloat162_rn(v.z * s, v.w * s);
        uint2 u;
        u.x = *reinterpret_cast<uint32_t*>(&a);
        u.y = *reinterpret_cast<uint32_t*>(&b);
        ((uint2*)(Wcat + (size_t)m * CD * CD))[i] = u;
    } else if (m == 3) {
        int i = bx * 256 + t;
        float4 v = ((const float4*)Wg)[i];
        ((uint32_t*)Og8)[i] = f4_to_e4m3x4(v.x * WSCALE, v.y * WSCALE, v.z * WSCALE, v.w * WSCALE);
    } else if (m == 4) {
        int i = bx * 256 + t;
        float4 v = ((const float4*)Wo)[i];
        __nv_bfloat162 a = __floats2bfloat162_rn(v.x, v.y);
        __nv_bfloat162 b = __floats2bfloat162_rn(v.z, v.w);
        uint2 u;
        u.x = *reinterpret_cast<uint32_t*>(&a);
        u.y = *reinterpret_cast<uint32_t*>(&b);
        ((uint2*)WoB)[i] = u;
    } else if (m == 5) {
        __shared__ float tile[32][33];
        int tr = bx >> 5;   // d tile
        int tc = bx & 31;   // c tile
        int r = t >> 3, cg = (t & 7) * 4;
        float4 v = *(const float4*)(Wk + (size_t)(tc * 32 + r) * CD + tr * 32 + cg);
        tile[r][cg] = v.x; tile[r][cg + 1] = v.y; tile[r][cg + 2] = v.z; tile[r][cg + 3] = v.w;
        __syncthreads();
        float o0 = tile[cg][r], o1 = tile[cg + 1][r], o2 = tile[cg + 2][r], o3 = tile[cg + 3][r];
        __nv_bfloat162 p0 = __floats2bfloat162_rn(o0, o1);
        __nv_bfloat162 p1 = __floats2bfloat162_rn(o2, o3);
        uint2 u;
        u.x = *reinterpret_cast<uint32_t*>(&p0);
        u.y = *reinterpret_cast<uint32_t*>(&p1);
        *(uint2*)(WkT + (size_t)(tr * 32 + r) * CD + tc * 32 + cg) = u;
    } else {
        __shared__ float tile[32][33];
        __shared__ float As_[32][9];
        __shared__ float Bs_[8][33];
        int tr = bx >> 5;   // d tile
        int tc = bx & 31;   // c tile
        int r = t >> 3, cg = (t & 7) * 4;
        float4 v = *(const float4*)(W0 + (size_t)(tc * 32 + r) * CD + tr * 32 + cg);
        tile[r][cg] = v.x; tile[r][cg + 1] = v.y; tile[r][cg + 2] = v.z; tile[r][cg + 3] = v.w;
        As_[t >> 3][t & 7] = Ai[(size_t)(tc * 32 + (t >> 3)) * 8 + (t & 7)];
        Bs_[t >> 5][t & 31] = Bi[(size_t)(t >> 5) * CD + tr * 32 + (t & 31)];
        __syncthreads();
        float o[4];
#pragma unroll
        for (int j = 0; j < 4; j++) {
            float val = tile[cg + j][r];
#pragma unroll
            for (int rr = 0; rr < 8; rr++) val += As_[cg + j][rr] * Bs_[rr][r];
            o[j] = val;
        }
        __nv_bfloat162 p0 = __floats2bfloat162_rn(o[0], o[1]);
        __nv_bfloat162 p1 = __floats2bfloat162_rn(o[2], o[3]);
        uint2 u;
        u.x = *reinterpret_cast<uint32_t*>(&p0);
        u.y = *reinterpret_cast<uint32_t*>(&p1);
        *(uint2*)(W0T + (size_t)(tr * 32 + r) * CD + tc * 32 + cg) = u;
    }
}

// ------------------- mma helpers -------------------
DEVINL void ldmx4(uint32_t* r, uint32_t addr) {
    asm volatile("ldmatrix.sync.aligned.m8n8.x4.shared.b16 {%0,%1,%2,%3}, [%4];"
                 : "=r"(r[0]), "=r"(r[1]), "=r"(r[2]), "=r"(r[3]) : "r"(addr));
}
DEVINL void mma16816(float* c, const uint32_t* a, uint32_t b0, uint32_t b1) {
    asm volatile(
        "mma.sync.aligned.m16n8k16.row.col.f32.bf16.bf16.f32 "
        "{%0,%1,%2,%3}, {%4,%5,%6,%7}, {%8,%9}, {%0,%1,%2,%3};"
        : "+f"(c[0]), "+f"(c[1]), "+f"(c[2]), "+f"(c[3])
        : "r"(a[0]), "r"(a[1]), "r"(a[2]), "r"(a[3]), "r"(b0), "r"(b1));
}
DEVINL void mma16832f8(float* c, const uint32_t* a, uint32_t b0, uint32_t b1) {
    asm volatile(
        "mma.sync.aligned.m16n8k32.row.col.f32.e4m3.e4m3.f32 "
        "{%0,%1,%2,%3}, {%4,%5,%6,%7}, {%8,%9}, {%0,%1,%2,%3};"
        : "+f"(c[0]), "+f"(c[1]), "+f"(c[2]), "+f"(c[3])
        : "r"(a[0]), "r"(a[1]), "r"(a[2]), "r"(a[3]), "r"(b0), "r"(b1));
}

// ===================================================================
// 64x128 CTA tile, 128 threads (4 warps, warp 32x64), 2-stage pipeline,
// 4 CTAs/SM. smem: A0=0(8K) A1=8192 B0=16384(16K) B1=32768 ; 48KB.
// ===================================================================
static constexpr uint32_t GF_SMEM = 49152;

DEVINL void bf16_mainloop64(uint32_t sb, const char* ga, const char* gb,
                            uint32_t so0, int wm, int wn, int l, float (&acc)[2][8][4]) {
    {
        uint32_t as = sb, bs = sb + 16384u;
#pragma unroll
        for (int j = 0; j < 4; j++) cpa16(as + so0 + j * 2048, ga + (size_t)j * 32768);
#pragma unroll
        for (int j = 0; j < 8; j++) cpa16(bs + so0 + j * 2048, gb + (size_t)j * 32768);
        asm volatile("cp.async.commit_group;" ::: "memory");
    }
    for (int kc = 0; kc < 16; kc++) {
        int buf = kc & 1;
        asm volatile("cp.async.wait_group 0;" ::: "memory");
        __syncthreads();
        if (kc + 1 < 16) {
            int nb = buf ^ 1;
            uint32_t as = sb + (uint32_t)(nb * 8192);
            uint32_t bs = sb + 16384u + (uint32_t)(nb * 16384);
#pragma unroll
            for (int j = 0; j < 4; j++)
                cpa16(as + so0 + j * 2048, ga + (size_t)j * 32768 + (kc + 1) * 128);
#pragma unroll
            for (int j = 0; j < 8; j++)
                cpa16(bs + so0 + j * 2048, gb + (size_t)j * 32768 + (kc + 1) * 128);
            asm volatile("cp.async.commit_group;" ::: "memory");
        }
        uint32_t aB = sb + (uint32_t)(buf * 8192);
        uint32_t bB = sb + 16384u + (uint32_t)(buf * 16384);
#pragma unroll
        for (int kk = 0; kk < 4; kk++) {
            uint32_t af[2][4], bfr[4][4];
#pragma unroll
            for (int mi = 0; mi < 2; mi++) {
                uint32_t r = (uint32_t)(wm * 32 + mi * 16 + (l & 15));
                uint32_t cb = (uint32_t)(kk * 32 + ((l >> 4) << 4));
                ldmx4(af[mi], aB + SWZ128(r * 128 + cb));
            }
#pragma unroll
            for (int np = 0; np < 4; np++) {
                uint32_t r = (uint32_t)(wn * 64 + np * 16 + (l & 7) + ((l >> 4) << 3));
                uint32_t cb = (uint32_t)(kk * 32 + (((l >> 3) & 1) << 4));
                ldmx4(bfr[np], bB + SWZ128(r * 128 + cb));
            }
#pragma unroll
            for (int mi = 0; mi < 2; mi++)
#pragma unroll
                for (int ni = 0; ni < 8; ni++) {
                    int np = ni >> 1;
                    mma16816(acc[mi][ni], af[mi],
                             bfr[np][(ni & 1) * 2], bfr[np][(ni & 1) * 2 + 1]);
                }
        }
    }
}

// ------------------- fp8 gate path (64x128 tile, 2-stage) -------------------
DEVINL void f8_gate_path(uint32_t sb, const uint8_t* __restrict__ Ag0,
                         const uint8_t* __restrict__ Bg0, uint8_t* __restrict__ out8,
                         int bx, int by) {
    int tid = threadIdx.x, l = tid & 31, w = tid >> 5;
    int wm = w & 1, wn = w >> 1;
    const uint8_t* Ag = Ag0 + (size_t)bx * 64 * CD;
    const uint8_t* Bg = Bg0 + (size_t)by * 128 * CD;

    float acc[2][8][4];
#pragma unroll
    for (int mi = 0; mi < 2; mi++)
#pragma unroll
        for (int ni = 0; ni < 8; ni++)
#pragma unroll
            for (int j = 0; j < 4; j++) acc[mi][ni][j] = 0.f;

    {
#pragma unroll
        for (int i = 0; i < 2; i++) {
            int idx = tid + 128 * i, row = idx >> 2, seg = idx & 3;
            cpa16(sb + (uint32_t)(row * 80 + seg * 16), Ag + (size_t)row * CD + seg * 16);
        }
#pragma unroll
        for (int i = 0; i < 4; i++) {
            int idx = tid + 128 * i, row = idx >> 2, seg = idx & 3;
            cpa16(sb + 10240u + (uint32_t)(row * 80 + seg * 16), Bg + (size_t)row * CD + seg * 16);
        }
        asm volatile("cp.async.commit_group;" ::: "memory");
    }

    for (int kc = 0; kc < 16; kc++) {
        int buf = kc & 1;
        asm volatile("cp.async.wait_group 0;" ::: "memory");
        __syncthreads();
        if (kc + 1 < 16) {
            int nb = buf ^ 1;
#pragma unroll
            for (int i = 0; i < 2; i++) {
                int idx = tid + 128 * i, row = idx >> 2, seg = idx & 3;
                cpa16(sb + (uint32_t)(nb * 5120 + row * 80 + seg * 16),
                      Ag + (size_t)row * CD + (kc + 1) * 64 + seg * 16);
            }
#pragma unroll
            for (int i = 0; i < 4; i++) {
                int idx = tid + 128 * i, row = idx >> 2, seg = idx & 3;
                cpa16(sb + 10240u + (uint32_t)(nb * 10240 + row * 80 + seg * 16),
                      Bg + (size_t)row * CD + (kc + 1) * 64 + seg * 16);
            }
            asm volatile("cp.async.commit_group;" ::: "memory");
        }
        uint32_t aB = sb + (uint32_t)(buf * 5120);
        uint32_t bB = sb + 10240u + (uint32_t)(buf * 10240);
#pragma unroll
        for (int kk = 0; kk < 2; kk++) {
            uint32_t af[2][4], bfr[4][4];
#pragma unroll
            for (int mi = 0; mi < 2; mi++) {
                uint32_t addr = aB + (uint32_t)((wm * 32 + mi * 16 + (l & 15)) * 80
                                                + kk * 32 + ((l >> 4) << 4));
                ldmx4(af[mi], addr);
            }
#pragma unroll
            for (int np = 0; np < 4; np++) {
                uint32_t addr = bB + (uint32_t)((wn * 64 + np * 16 + (l & 7) + ((l >> 4) << 3)) * 80
                                                + kk * 32 + (((l >> 3) & 1) << 4));
                ldmx4(bfr[np], addr);
            }
#pragma unroll
            for (int mi = 0; mi < 2; mi++)
#pragma unroll
                for (int ni = 0; ni < 8; ni++) {
                    int np = ni >> 1;
                    mma16832f8(acc[mi][ni], af[mi],
                               bfr[np][(ni & 1) * 2], bfr[np][(ni & 1) * 2 + 1]);
                }
        }
    }

    int brow = bx * 64 + wm * 32;
    int bcol = by * 128 + wn * 64;
#pragma unroll
    for (int mi = 0; mi < 2; mi++) {
#pragma unroll
        for (int ni = 0; ni < 8; ni++) {
            int r0 = brow + mi * 16 + (l >> 2);
            int col = bcol + ni * 8 + (l & 3) * 2;
            float c0 = 1.f / (1.f + expf(-acc[mi][ni][0] * INV_WSCALE));
            float c1 = 1.f / (1.f + expf(-acc[mi][ni][1] * INV_WSCALE));
            float c2 = 1.f / (1.f + expf(-acc[mi][ni][2] * INV_WSCALE));
            float c3 = 1.f / (1.f + expf(-acc[mi][ni][3] * INV_WSCALE));
            *(uint16_t*)(out8 + (size_t)r0 * CD + col) = f2e4m3x2(c0, c1);
            *(uint16_t*)(out8 + (size_t)(r0 + 8) * CD + col) = f2e4m3x2(c2, c3);
        }
    }
}

// ------------------- y0-weight GEMM + WE fold -------------------
// grid (16, 8). Wy0[d][c] = sum_e W0T[d][e]*WkT[c][e].
// Epilogue: Wcat[3072+d] = Wy0 ; Wcat[2048+d] = Wy0 - Wv(old Wcat[2048+d]).
__global__ void __launch_bounds__(128, 4) gemm_we(
    const __nv_bfloat16* __restrict__ W0T, const __nv_bfloat16* __restrict__ WkT,
    __nv_bfloat16* __restrict__ Wcat) {
    extern __shared__ __align__(1024) unsigned char smem[];
    uint32_t sb = s2u(smem);
    int tid = threadIdx.x;
    int l = tid & 31, w = tid >> 5;
    int wm = w & 1, wn = w >> 1;

    int r0l = tid >> 3, segl = tid & 7;
    const char* ga = (const char*)(W0T + (size_t)blockIdx.x * 64 * CD) + r0l * 2048 + segl * 16;
    const char* gb = (const char*)(WkT + (size_t)blockIdx.y * 128 * CD) + r0l * 2048 + segl * 16;
    uint32_t so0 = SWZ128((uint32_t)(r0l * 128 + segl * 16));

    float acc[2][8][4];
#pragma unroll
    for (int mi = 0; mi < 2; mi++)
#pragma unroll
        for (int ni = 0; ni < 8; ni++)
#pragma unroll
            for (int j = 0; j < 4; j++) acc[mi][ni][j] = 0.f;

    bf16_mainloop64(sb, ga, gb, so0, wm, wn, l, acc);

    int brow = blockIdx.x * 64 + wm * 32;
    int bcol = blockIdx.y * 128 + wn * 64;
#pragma unroll
    for (int mi = 0; mi < 2; mi++) {
#pragma unroll
        for (int ni = 0; ni < 8; ni++) {
            int r0 = brow + mi * 16 + (l >> 2);
            int col = bcol + ni * 8 + (l & 3) * 2;
#pragma unroll
            for (int hh = 0; hh < 2; hh++) {
                int r = r0 + hh * 8;
                float a0 = acc[mi][ni][hh * 2], a1 = acc[mi][ni][hh * 2 + 1];
                __nv_bfloat162 vv = *(const __nv_bfloat162*)(Wcat + (size_t)(2048 + r) * CD + col);
                __nv_bfloat162 py = __floats2bfloat162_rn(a0, a1);
                __nv_bfloat162 pe = __floats2bfloat162_rn(a0 - __bfloat162float(vv.x),
                                                          a1 - __bfloat162float(vv.y));
                *(__nv_bfloat162*)(Wcat + (size_t)(3072 + r) * CD + col) = py;
                *(__nv_bfloat162*)(Wcat + (size_t)(2048 + r) * CD + col) = pe;
            }
        }
    }
}

// ------------------- fused GEMM kernel -------------------
// by 0..15  : Q|K -> e4m3 QK8 (stride N2)
// by 16..23 : E   -> bf16 Eb (stride CD)   (B rows 2048..3071 of Wcat)
// by 24..31 : Y   -> e4m3 Y8 (stride CD)   (B rows 3072..4095 of Wcat)
// by 32..39 : gate fp8 path
__global__ void __launch_bounds__(128, 4) gemm_fused(
    const __nv_bfloat16* __restrict__ A, const __nv_bfloat16* __restrict__ Bw,
    uint8_t* __restrict__ QK8, __nv_bfloat16* __restrict__ Eb, uint8_t* __restrict__ Y8,
    const uint8_t* __restrict__ A8, const uint8_t* __restrict__ B8,
    uint8_t* __restrict__ G8) {
    extern __shared__ __align__(1024) unsigned char smem[];
    uint32_t sb = s2u(smem);
    int by = (int)blockIdx.y;
    if (by >= 32) {
        f8_gate_path(sb, A8, B8, G8, blockIdx.x, by - 32);
        return;
    }
    int tid = threadIdx.x;
    int l = tid & 31, w = tid >> 5;
    int wm = w & 1, wn = w >> 1;

    int r0l = tid >> 3, segl = tid & 7;
    const char* ga = (const char*)(A + (size_t)blockIdx.x * 64 * CD) + r0l * 2048 + segl * 16;
    const char* gb = (const char*)(Bw + (size_t)by * 128 * CD) + r0l * 2048 + segl * 16;
    uint32_t so0 = SWZ128((uint32_t)(r0l * 128 + segl * 16));

    float acc[2][8][4];
#pragma unroll
    for (int mi = 0; mi < 2; mi++)
#pragma unroll
        for (int ni = 0; ni < 8; ni++)
#pragma unroll
            for (int j = 0; j < 4; j++) acc[mi][ni][j] = 0.f;

    bf16_mainloop64(sb, ga, gb, so0, wm, wn, l, acc);

    int brow = blockIdx.x * 64 + wm * 32;
    if (by < 16) {
        int bcol = by * 128 + wn * 64;
#pragma unroll
        for (int mi = 0; mi < 2; mi++) {
#pragma unroll
            for (int ni = 0; ni < 8; ni++) {
                int r0 = brow + mi * 16 + (l >> 2);
                int col = bcol + ni * 8 + (l & 3) * 2;
                *(uint16_t*)(QK8 + (size_t)r0 * N2 + col) =
                    f2e4m3x2(acc[mi][ni][0], acc[mi][ni][1]);
                *(uint16_t*)(QK8 + (size_t)(r0 + 8) * N2 + col) =
                    f2e4m3x2(acc[mi][ni][2], acc[mi][ni][3]);
            }
        }
    } else if (by < 24) {
        int bcol = (by - 16) * 128 + wn * 64;
#pragma unroll
        for (int mi = 0; mi < 2; mi++) {
#pragma unroll
            for (int ni = 0; ni < 8; ni++) {
                int r0 = brow + mi * 16 + (l >> 2);
                int col = bcol + ni * 8 + (l & 3) * 2;
                __nv_bfloat162 p0 = __floats2bfloat162_rn(acc[mi][ni][0], acc[mi][ni][1]);
                __nv_bfloat162 p1 = __floats2bfloat162_rn(acc[mi][ni][2], acc[mi][ni][3]);
                *(__nv_bfloat162*)(Eb + (size_t)r0 * CD + col) = p0;
                *(__nv_bfloat162*)(Eb + (size_t)(r0 + 8) * CD + col) = p1;
            }
        }
    } else {
        int bcol = (by - 24) * 128 + wn * 64;
#pragma unroll
        for (int mi = 0; mi < 2; mi++) {
#pragma unroll
            for (int ni = 0; ni < 8; ni++) {
                int r0 = brow + mi * 16 + (l >> 2);
                int col = bcol + ni * 8 + (l & 3) * 2;
                *(uint16_t*)(Y8 + (size_t)r0 * CD + col) =
                    f2e4m3x2(acc[mi][ni][0], acc[mi][ni][1]);
                *(uint16_t*)(Y8 + (size_t)(r0 + 8) * CD + col) =
                    f2e4m3x2(acc[mi][ni][2], acc[mi][ni][3]);
            }
        }
    }
}

// ------------------- final bf16 GEMM: out = x + (og@Wo^T)*ls_g -------------------
__global__ void __launch_bounds__(128, 4) gemm_bf16_fin(
    const __nv_bfloat16* __restrict__ A, const __nv_bfloat16* __restrict__ Bw,
    float* __restrict__ outf, const float* __restrict__ evec,
    const float* __restrict__ xres) {
    extern __shared__ __align__(1024) unsigned char smem[];
    uint32_t sb = s2u(smem);
    int tid = threadIdx.x;
    int l = tid & 31, w = tid >> 5;
    int wm = w & 1, wn = w >> 1;

    int r0l = tid >> 3, segl = tid & 7;
    const char* ga = (const char*)(A + (size_t)blockIdx.x * 64 * CD) + r0l * 2048 + segl * 16;
    const char* gb = (const char*)(Bw + (size_t)blockIdx.y * 128 * CD) + r0l * 2048 + segl * 16;
    uint32_t so0 = SWZ128((uint32_t)(r0l * 128 + segl * 16));

    float acc[2][8][4];
#pragma unroll
    for (int mi = 0; mi < 2; mi++)
#pragma unroll
        for (int ni = 0; ni < 8; ni++)
#pragma unroll
            for (int j = 0; j < 4; j++) acc[mi][ni][j] = 0.f;

    bf16_mainloop64(sb, ga, gb, so0, wm, wn, l, acc);

    int brow = blockIdx.x * 64 + wm * 32;
    int bcol = blockIdx.y * 128 + wn * 64;
#pragma unroll
    for (int mi = 0; mi < 2; mi++) {
#pragma unroll
        for (int ni = 0; ni < 8; ni++) {
            int r0 = brow + mi * 16 + (l >> 2);
            int col = bcol + ni * 8 + (l & 3) * 2;
            float e0 = evec[col], e1 = evec[col + 1];
            float2 xv0 = *(const float2*)(xres + (size_t)r0 * CD + col);
            *(float2*)(outf + (size_t)r0 * CD + col) =
                make_float2(xv0.x + acc[mi][ni][0] * e0, xv0.y + acc[mi][ni][1] * e1);
            float2 xv1 = *(const float2*)(xres + (size_t)(r0 + 8) * CD + col);
            *(float2*)(outf + (size_t)(r0 + 8) * CD + col) =
                make_float2(xv1.x + acc[mi][ni][2] * e0, xv1.y + acc[mi][ni][3] * e1);
        }
    }
}

// ------------------- scan kernels -------------------
// QK8: [row][Q|K] e4m3 stride 2048;  Eb: [row][E] bf16 stride 1024;  Y8: e4m3 stride 1024

// pass 1: raw chunk sums of k*e + loss. grid (NCH, BN), 1024 thr
__global__ void __launch_bounds__(1024) scan_p1(
    const uint8_t* __restrict__ QK8, const __nv_bfloat16* __restrict__ Eb,
    float* __restrict__ cs, float* __restrict__ loss_slot) {
    int b = blockIdx.y, ch = blockIdx.x, c = threadIdx.x;
    size_t base2 = ((size_t)(b * TNseq + ch * CHL)) * N2 + c;
    size_t base1 = ((size_t)(b * TNseq + ch * CHL)) * CD + c;
    float s = 0.f, lsum = 0.f;
#pragma unroll 4
    for (int t = 0; t < CHL; t++) {
        float k = e4m3_to_f(QK8[base2 + (size_t)t * N2 + 1024]);
        float e = __bfloat162float(Eb[base1 + (size_t)t * CD]);
        lsum += e * e;
        s += k * e;
    }
    cs[((size_t)b * NCH + ch) * CD + c] = s;
#pragma unroll
    for (int o = 16; o > 0; o >>= 1) lsum += __shfl_xor_sync(0xffffffffu, lsum, o);
    __shared__ float red[32];
    int wid = c >> 5;
    if ((c & 31) == 0) red[wid] = lsum;
    __syncthreads();
    if (c < 32) {
        float v2 = red[c];
#pragma unroll
        for (int o = 16; o > 0; o >>= 1) v2 += __shfl_xor_sync(0xffffffffu, v2, o);
        if (c == 0) atomicAdd(loss_slot, v2 * (1.f / 16777216.f));
    }
}

// pass 2 (fused prefix): each block sums cs of preceding chunks, then replays.
__global__ void __launch_bounds__(1024) scan_p3(
    const uint8_t* __restrict__ QK8, const __nv_bfloat16* __restrict__ Eb,
    const uint8_t* __restrict__ Y8, const uint8_t* __restrict__ Gt8,
    const float* __restrict__ cs, __nv_bfloat16* __restrict__ ogb) {
    __shared__ float ps_s[CHL];
    int b = blockIdx.y, ch = blockIdx.x, c = threadIdx.x;
    if (c < CHL) {
        int gt = ch * CHL + c;
        ps_s[c] = 1.f / (1.f + 0.1f * logf((float)(gt + 1)));
    }
    __syncthreads();
    float run = 0.f;
    for (int j = 0; j < ch; j++) run += cs[((size_t)b * NCH + j) * CD + c];
    size_t base2 = ((size_t)(b * TNseq + ch * CHL)) * N2 + c;
    size_t base1 = ((size_t)(b * TNseq + ch * CHL)) * CD + c;
#pragma unroll 4
    for (int t = 0; t < CHL; t++) {
        size_t i2 = base2 + (size_t)t * N2;
        size_t i1 = base1 + (size_t)t * CD;
        float q = e4m3_to_f(QK8[i2]);
        float k = e4m3_to_f(QK8[i2 + 1024]);
        float e = __bfloat162float(Eb[i1]);
        float y = e4m3_to_f(Y8[i1]);
        float g = e4m3_to_f(Gt8[i1]);
        float op = (y - q * run * ps_s[t]) * g;
        ogb[i1] = __float2bfloat16(op);
        run += k * e;
    }
}

// ------------------- launch -------------------
extern "C" void kernel_launch(void* const* d_in, const int* in_sizes, int n_in,
                              void* d_out, int out_size) {
    const float* x     = (const float*)d_in[0];
    const float* W0    = (const float*)d_in[1];
    const float* Ai    = (const float*)d_in[2];
    const float* Bi    = (const float*)d_in[3];
    const float* loglr = (const float*)d_in[4];
    const float* Wq    = (const float*)d_in[5];
    const float* Wk    = (const float*)d_in[6];
    const float* Wv    = (const float*)d_in[7];
    const float* Wo    = (const float*)d_in[8];
    const float* Wg    = (const float*)d_in[9];
    const float* lng   = (const float*)d_in[10];
    const float* lnb   = (const float*)d_in[11];
    const float* lsg   = (const float*)d_in[12];
    float* out = (float*)d_out;
    float* loss_slot = out + (out_size - 1);

    unsigned char* sc = nullptr;
    cudaGetSymbolAddress((void**)&sc, g_scratch);

    uint8_t*       QK8  = (uint8_t*)(sc + OFF_QK8);
    __nv_bfloat16* Eb   = (__nv_bfloat16*)(sc + OFF_E);
    uint8_t*       Y8   = (uint8_t*)(sc + OFF_Y8);
    __nv_bfloat16* Hb   = (__nv_bfloat16*)(sc + OFF_H);
    uint8_t*       X8   = (uint8_t*)(sc + OFF_X8);
    uint8_t*       G8   = (uint8_t*)(sc + OFF_G8);
    __nv_bfloat16* OGb  = (__nv_bfloat16*)(sc + OFF_OGB);
    __nv_bfloat16* Wcat = (__nv_bfloat16*)(sc + OFF_WCAT);
    __nv_bfloat16* WkT  = (__nv_bfloat16*)(sc + OFF_WKT);
    __nv_bfloat16* W0T  = (__nv_bfloat16*)(sc + OFF_W0T);
    uint8_t*       Wg8  = (uint8_t*)(sc + OFF_WG8);
    __nv_bfloat16* WoB  = (__nv_bfloat16*)(sc + OFF_WOB);
    float* cs = (float*)(sc + OFF_CS);

    cudaFuncSetAttribute(gemm_fused, cudaFuncAttributeMaxDynamicSharedMemorySize, GF_SMEM);
    cudaFuncSetAttribute(gemm_we, cudaFuncAttributeMaxDynamicSharedMemorySize, GF_SMEM);
    cudaFuncSetAttribute(gemm_bf16_fin, cudaFuncAttributeMaxDynamicSharedMemorySize, GF_SMEM);

    // 1: fused layernorm + all weight prep
    prep_all<<<MR + 7 * 1024, 256>>>(x, lng, lnb, Hb, X8,
                                     Wq, Wk, Wv, Wg, Wo, W0, Ai, Bi, loglr,
                                     Wcat, Wg8, WoB, WkT, W0T, loss_slot);
    // 2: y0 weight + WE fold
    gemm_we<<<dim3(16, 8), 128, GF_SMEM>>>(W0T, WkT, Wcat);
    // 3: big fused GEMM: Q|K e4m3 + E bf16 + Y e4m3 + gate fp8
    gemm_fused<<<dim3(MR / 64, 40), 128, GF_SMEM>>>(Hb, Wcat, QK8, Eb, Y8, X8, Wg8, G8);
    // 4: chunk sums + loss
    scan_p1<<<dim3(NCH, BN), 1024>>>(QK8, Eb, cs, loss_slot);
    // 5: prefix + replay -> og
    scan_p3<<<dim3(NCH, BN), 1024>>>(QK8, Eb, Y8, G8, cs, OGb);
    // 6: out = x + (og @ Wo^T) * ls_g
    gemm_bf16_fin<<<dim3(MR / 64, CD / 128), 128, GF_SMEM>>>(OGb, WoB, out, lsg, x);
}

// round 15
// speedup vs baseline: 1.0166x; 1.0166x over previous
#include <cuda_runtime.h>
#include <cuda_bf16.h>
#include <cstdint>

#define DEVINL __device__ __forceinline__

static constexpr int CD = 1024;          // channel dim
static constexpr int BN = 4;             // batch
static constexpr int TNseq = 4096;       // seq len
static constexpr int MR = BN * TNseq;    // 16384 rows
static constexpr int NCH = 64;           // scan chunks
static constexpr int CHL = TNseq / NCH;  // 64 steps/chunk
static constexpr int N2 = 2048;          // QK8 / EY row stride

// ------------------- scratch -------------------
static constexpr size_t MB  = 1024ull * 1024ull;
static constexpr size_t OFF_QK8  = 0;          // Q|K e4m3 [MR][2048]   32MB
static constexpr size_t OFF_EY   = 32  * MB;   // E|Y bf16 [MR][2048]   64MB
static constexpr size_t OFF_H    = 96  * MB;   // h bf16                32MB
static constexpr size_t OFF_X8   = 128 * MB;   // x e4m3                16MB
static constexpr size_t OFF_G8   = 144 * MB;   // gate e4m3             16MB
static constexpr size_t OFF_OGB  = 160 * MB;   // (out*gate) bf16       32MB
static constexpr size_t OFF_WCAT = 192 * MB;   // Wcat bf16 [4096][1024] 8MB
static constexpr size_t OFF_WKT  = 200 * MB;   // Wk^T bf16 2MB
static constexpr size_t OFF_W0T  = 202 * MB;   // (W0+A@B)^T bf16 2MB
static constexpr size_t OFF_WG8  = 204 * MB;   // Wg e4m3*16 1MB
static constexpr size_t OFF_WOB  = 205 * MB;   // Wo bf16 2MB
static constexpr size_t OFF_CS   = 207 * MB;   // 1MB fp32 raw chunk sums
static constexpr size_t SCRATCH  = 208 * MB;
__device__ __align__(1024) unsigned char g_scratch[SCRATCH];

static constexpr float WSCALE = 16.0f;
static constexpr float INV_WSCALE = 1.0f / 16.0f;

// ------------------- helpers -------------------
DEVINL uint32_t s2u(const void* p) {
    uint32_t a;
    asm("{ .reg .u64 t; cvta.to.shared.u64 t, %1; cvt.u32.u64 %0, t; }" : "=r"(a) : "l"(p));
    return a;
}
DEVINL uint16_t f2e4m3x2(float lo, float hi) {
    uint16_t r;
    asm("cvt.rn.satfinite.e4m3x2.f32 %0, %1, %2;" : "=h"(r) : "f"(hi), "f"(lo));
    return r;
}
DEVINL uint32_t f4_to_e4m3x4(float a, float b, float c, float d) {
    uint32_t lo = f2e4m3x2(a, b);
    uint32_t hi = f2e4m3x2(c, d);
    return lo | (hi << 16);
}
DEVINL float e4m3_to_f(uint8_t b) {
    uint16_t s = (uint16_t)b;
    uint32_t h2;
    asm("cvt.rn.f16x2.e4m3x2 %0, %1;" : "=r"(h2) : "h"(s));
    __half h = *reinterpret_cast<__half*>(&h2);   // low half = low byte
    return __half2float(h);
}
#define SWZ128(x) ((x) ^ (((x) >> 3) & 0x70))
DEVINL void cpa16(uint32_t s, const void* g) {
    asm volatile("cp.async.cg.shared.global [%0], [%1], 16;" :: "r"(s), "l"(g));
}

// ------------------- unified weight prep -------------------
// grid (1024, 7), 256 threads.
// m=0: Wq*min(exp(loglr),1) -> Wcat[0:1024) bf16
// m=1: Wk -> Wcat[1024:2048) bf16
// m=2: Wv -> Wcat[2048:3072) bf16   (later overwritten by WE = Wy0 - Wv)
// m=3: Wg*16 -> fp8
// m=4: Wo -> bf16 WoB
// m=5: WkT[d][c] = Wk[c][d] bf16
// m=6: W0T[d][c] = W0[c][d] + sum_r A[c][r]*B[r][d] bf16
__global__ void __launch_bounds__(256) wprep_all(
    const float* __restrict__ Wq, const float* __restrict__ Wk, const float* __restrict__ Wv,
    const float* __restrict__ Wg, const float* __restrict__ Wo, const float* __restrict__ W0,
    const float* __restrict__ Ai, const float* __restrict__ Bi, const float* __restrict__ loglr,
    __nv_bfloat16* __restrict__ Wcat, uint8_t* __restrict__ Og8, __nv_bfloat16* __restrict__ WoB,
    __nv_bfloat16* __restrict__ WkT, __nv_bfloat16* __restrict__ W0T) {
    int m = blockIdx.y;
    int tid = threadIdx.x;
    if (m < 3) {
        int i = blockIdx.x * 256 + tid;   // float4 index
        const float* W = (m == 0) ? Wq : (m == 1) ? Wk : Wv;
        float4 v = ((const float4*)W)[i];
        float s = 1.0f;
        if (m == 0) s = fminf(expf(loglr[i >> 8]), 1.0f);
        __nv_bfloat162 a = __floats2bfloat162_rn(v.x * s, v.y * s);
        __nv_bfloat162 b = __floats2bfloat162_rn(v.z * s, v.w * s);
        uint2 u;
        u.x = *reinterpret_cast<uint32_t*>(&a);
        u.y = *reinterpret_cast<uint32_t*>(&b);
        ((uint2*)(Wcat + (size_t)m * CD * CD))[i] = u;
    } else if (m == 3) {
        int i = blockIdx.x * 256 + tid;
        float4 v = ((const float4*)Wg)[i];
        ((uint32_t*)Og8)[i] = f4_to_e4m3x4(v.x * WSCALE, v.y * WSCALE, v.z * WSCALE, v.w * WSCALE);
    } else if (m == 4) {
        int i = blockIdx.x * 256 + tid;
        float4 v = ((const float4*)Wo)[i];
        __nv_bfloat162 a = __floats2bfloat162_rn(v.x, v.y);
        __nv_bfloat162 b = __floats2bfloat162_rn(v.z, v.w);
        uint2 u;
        u.x = *reinterpret_cast<uint32_t*>(&a);
        u.y = *reinterpret_cast<uint32_t*>(&b);
        ((uint2*)WoB)[i] = u;
    } else if (m == 5) {
        __shared__ float tile[32][33];
        int tr = blockIdx.x >> 5;   // d tile
        int tc = blockIdx.x & 31;   // c tile
        int r = tid >> 3, cg = (tid & 7) * 4;
        float4 v = *(const float4*)(Wk + (size_t)(tc * 32 + r) * CD + tr * 32 + cg);
        tile[r][cg] = v.x; tile[r][cg + 1] = v.y; tile[r][cg + 2] = v.z; tile[r][cg + 3] = v.w;
        __syncthreads();
        float o0 = tile[cg][r], o1 = tile[cg + 1][r], o2 = tile[cg + 2][r], o3 = tile[cg + 3][r];
        __nv_bfloat162 p0 = __floats2bfloat162_rn(o0, o1);
        __nv_bfloat162 p1 = __floats2bfloat162_rn(o2, o3);
        uint2 u;
        u.x = *reinterpret_cast<uint32_t*>(&p0);
        u.y = *reinterpret_cast<uint32_t*>(&p1);
        *(uint2*)(WkT + (size_t)(tr * 32 + r) * CD + tc * 32 + cg) = u;
    } else {
        __shared__ float tile[32][33];
        __shared__ float As_[32][9];
        __shared__ float Bs_[8][33];
        int tr = blockIdx.x >> 5;   // d tile
        int tc = blockIdx.x & 31;   // c tile
        int r = tid >> 3, cg = (tid & 7) * 4;
        float4 v = *(const float4*)(W0 + (size_t)(tc * 32 + r) * CD + tr * 32 + cg);
        tile[r][cg] = v.x; tile[r][cg + 1] = v.y; tile[r][cg + 2] = v.z; tile[r][cg + 3] = v.w;
        As_[tid >> 3][tid & 7] = Ai[(size_t)(tc * 32 + (tid >> 3)) * 8 + (tid & 7)];
        Bs_[tid >> 5][tid & 31] = Bi[(size_t)(tid >> 5) * CD + tr * 32 + (tid & 31)];
        __syncthreads();
        float o[4];
#pragma unroll
        for (int j = 0; j < 4; j++) {
            float val = tile[cg + j][r];
#pragma unroll
            for (int rr = 0; rr < 8; rr++) val += As_[cg + j][rr] * Bs_[rr][r];
            o[j] = val;
        }
        __nv_bfloat162 p0 = __floats2bfloat162_rn(o[0], o[1]);
        __nv_bfloat162 p1 = __floats2bfloat162_rn(o[2], o[3]);
        uint2 u;
        u.x = *reinterpret_cast<uint32_t*>(&p0);
        u.y = *reinterpret_cast<uint32_t*>(&p1);
        *(uint2*)(W0T + (size_t)(tr * 32 + r) * CD + tc * 32 + cg) = u;
    }
}

// fused layernorm: emit h bf16, x e4m3; extra blocks: WE = Wy0 - Wv; block0 zeroes loss.
// grid MR + 1024, block 256
__global__ void __launch_bounds__(256) ln_prep(const float* __restrict__ x,
                                               const float* __restrict__ lng,
                                               const float* __restrict__ lnb,
                                               __nv_bfloat16* __restrict__ hb,
                                               uint8_t* __restrict__ x8,
                                               __nv_bfloat16* __restrict__ Wcat,
                                               float* __restrict__ loss_slot) {
    int row = blockIdx.x;
    int t = threadIdx.x;
    if (row >= MR) {
        int d = row - MR;
        const __nv_bfloat16* wy = Wcat + (size_t)(3072 + d) * CD;
        __nv_bfloat16* we = Wcat + (size_t)(2048 + d) * CD;
        int c = t * 4;
        uint2 uy = *(const uint2*)(wy + c);
        uint2 uv = *(const uint2*)(we + c);
        __nv_bfloat162 y0 = *reinterpret_cast<__nv_bfloat162*>(&uy.x);
        __nv_bfloat162 y1 = *reinterpret_cast<__nv_bfloat162*>(&uy.y);
        __nv_bfloat162 v0 = *reinterpret_cast<__nv_bfloat162*>(&uv.x);
        __nv_bfloat162 v1 = *reinterpret_cast<__nv_bfloat162*>(&uv.y);
        __nv_bfloat162 e0 = __floats2bfloat162_rn(__bfloat162float(y0.x) - __bfloat162float(v0.x),
                                                  __bfloat162float(y0.y) - __bfloat162float(v0.y));
        __nv_bfloat162 e1 = __floats2bfloat162_rn(__bfloat162float(y1.x) - __bfloat162float(v1.x),
                                                  __bfloat162float(y1.y) - __bfloat162float(v1.y));
        uint2 ue;
        ue.x = *reinterpret_cast<uint32_t*>(&e0);
        ue.y = *reinterpret_cast<uint32_t*>(&e1);
        *(uint2*)(we + c) = ue;
        return;
    }
    if (row == 0 && t == 0) *loss_slot = 0.0f;
    const float4 v = ((const float4*)(x + (size_t)row * CD))[t];
    float s = v.x + v.y + v.z + v.w;
    float q = v.x * v.x + v.y * v.y + v.z * v.z + v.w * v.w;
#pragma unroll
    for (int o = 16; o > 0; o >>= 1) {
        s += __shfl_xor_sync(0xffffffffu, s, o);
        q += __shfl_xor_sync(0xffffffffu, q, o);
    }
    __shared__ float red[16];
    int wid = t >> 5;
    if ((t & 31) == 0) { red[wid] = s; red[8 + wid] = q; }
    __syncthreads();
    float ts = 0.f, tq = 0.f;
#pragma unroll
    for (int i = 0; i < 8; i++) { ts += red[i]; tq += red[8 + i]; }
    float mu = ts * (1.f / 1024.f);
    float var = tq * (1.f / 1024.f) - mu * mu;
    float rs = rsqrtf(var + 1e-5f);
    const float4 gv = ((const float4*)lng)[t];
    const float4 bv = ((const float4*)lnb)[t];
    float h0 = (v.x - mu) * rs * gv.x + bv.x;
    float h1 = (v.y - mu) * rs * gv.y + bv.y;
    float h2 = (v.z - mu) * rs * gv.z + bv.z;
    float h3 = (v.w - mu) * rs * gv.w + bv.w;
    __nv_bfloat162 ha = __floats2bfloat162_rn(h0, h1);
    __nv_bfloat162 hc = __floats2bfloat162_rn(h2, h3);
    uint2 hu; hu.x = *reinterpret_cast<uint32_t*>(&ha); hu.y = *reinterpret_cast<uint32_t*>(&hc);
    ((uint2*)(hb + (size_t)row * CD))[t] = hu;
    ((uint32_t*)(x8 + (size_t)row * CD))[t] = f4_to_e4m3x4(v.x, v.y, v.z, v.w);
}

// ------------------- mma helpers -------------------
DEVINL void ldmx4(uint32_t* r, uint32_t addr) {
    asm volatile("ldmatrix.sync.aligned.m8n8.x4.shared.b16 {%0,%1,%2,%3}, [%4];"
                 : "=r"(r[0]), "=r"(r[1]), "=r"(r[2]), "=r"(r[3]) : "r"(addr));
}
DEVINL void mma16816(float* c, const uint32_t* a, uint32_t b0, uint32_t b1) {
    asm volatile(
        "mma.sync.aligned.m16n8k16.row.col.f32.bf16.bf16.f32 "
        "{%0,%1,%2,%3}, {%4,%5,%6,%7}, {%8,%9}, {%0,%1,%2,%3};"
        : "+f"(c[0]), "+f"(c[1]), "+f"(c[2]), "+f"(c[3])
        : "r"(a[0]), "r"(a[1]), "r"(a[2]), "r"(a[3]), "r"(b0), "r"(b1));
}
DEVINL void mma16832f8(float* c, const uint32_t* a, uint32_t b0, uint32_t b1) {
    asm volatile(
        "mma.sync.aligned.m16n8k32.row.col.f32.e4m3.e4m3.f32 "
        "{%0,%1,%2,%3}, {%4,%5,%6,%7}, {%8,%9}, {%0,%1,%2,%3};"
        : "+f"(c[0]), "+f"(c[1]), "+f"(c[2]), "+f"(c[3])
        : "r"(a[0]), "r"(a[1]), "r"(a[2]), "r"(a[3]), "r"(b0), "r"(b1));
}

// ===================================================================
// 64x128 CTA tile, 128 threads (4 warps, warp 32x64), 2-stage pipeline,
// 4 CTAs/SM. smem: A0=0(8K) A1=8192 B0=16384(16K) B1=32768 ; 48KB.
// ===================================================================
static constexpr uint32_t GF_SMEM = 49152;

DEVINL void bf16_mainloop64(uint32_t sb, const char* ga, const char* gb,
                            uint32_t so0, int wm, int wn, int l, float (&acc)[2][8][4]) {
    {
        uint32_t as = sb, bs = sb + 16384u;
#pragma unroll
        for (int j = 0; j < 4; j++) cpa16(as + so0 + j * 2048, ga + (size_t)j * 32768);
#pragma unroll
        for (int j = 0; j < 8; j++) cpa16(bs + so0 + j * 2048, gb + (size_t)j * 32768);
        asm volatile("cp.async.commit_group;" ::: "memory");
    }
    for (int kc = 0; kc < 16; kc++) {
        int buf = kc & 1;
        asm volatile("cp.async.wait_group 0;" ::: "memory");
        __syncthreads();
        if (kc + 1 < 16) {
            int nb = buf ^ 1;
            uint32_t as = sb + (uint32_t)(nb * 8192);
            uint32_t bs = sb + 16384u + (uint32_t)(nb * 16384);
#pragma unroll
            for (int j = 0; j < 4; j++)
                cpa16(as + so0 + j * 2048, ga + (size_t)j * 32768 + (kc + 1) * 128);
#pragma unroll
            for (int j = 0; j < 8; j++)
                cpa16(bs + so0 + j * 2048, gb + (size_t)j * 32768 + (kc + 1) * 128);
            asm volatile("cp.async.commit_group;" ::: "memory");
        }
        uint32_t aB = sb + (uint32_t)(buf * 8192);
        uint32_t bB = sb + 16384u + (uint32_t)(buf * 16384);
#pragma unroll
        for (int kk = 0; kk < 4; kk++) {
            uint32_t af[2][4], bfr[4][4];
#pragma unroll
            for (int mi = 0; mi < 2; mi++) {
                uint32_t r = (uint32_t)(wm * 32 + mi * 16 + (l & 15));
                uint32_t cb = (uint32_t)(kk * 32 + ((l >> 4) << 4));
                ldmx4(af[mi], aB + SWZ128(r * 128 + cb));
            }
#pragma unroll
            for (int np = 0; np < 4; np++) {
                uint32_t r = (uint32_t)(wn * 64 + np * 16 + (l & 7) + ((l >> 4) << 3));
                uint32_t cb = (uint32_t)(kk * 32 + (((l >> 3) & 1) << 4));
                ldmx4(bfr[np], bB + SWZ128(r * 128 + cb));
            }
#pragma unroll
            for (int mi = 0; mi < 2; mi++)
#pragma unroll
                for (int ni = 0; ni < 8; ni++) {
                    int np = ni >> 1;
                    mma16816(acc[mi][ni], af[mi],
                             bfr[np][(ni & 1) * 2], bfr[np][(ni & 1) * 2 + 1]);
                }
        }
    }
}

// ------------------- fp8 gate path (64x128 tile, 2-stage) -------------------
DEVINL void f8_gate_path(uint32_t sb, const uint8_t* __restrict__ Ag0,
                         const uint8_t* __restrict__ Bg0, uint8_t* __restrict__ out8,
                         int bx, int by) {
    int tid = threadIdx.x, l = tid & 31, w = tid >> 5;
    int wm = w & 1, wn = w >> 1;
    const uint8_t* Ag = Ag0 + (size_t)bx * 64 * CD;
    const uint8_t* Bg = Bg0 + (size_t)by * 128 * CD;

    float acc[2][8][4];
#pragma unroll
    for (int mi = 0; mi < 2; mi++)
#pragma unroll
        for (int ni = 0; ni < 8; ni++)
#pragma unroll
            for (int j = 0; j < 4; j++) acc[mi][ni][j] = 0.f;

    {
#pragma unroll
        for (int i = 0; i < 2; i++) {
            int idx = tid + 128 * i, row = idx >> 2, seg = idx & 3;
            cpa16(sb + (uint32_t)(row * 80 + seg * 16), Ag + (size_t)row * CD + seg * 16);
        }
#pragma unroll
        for (int i = 0; i < 4; i++) {
            int idx = tid + 128 * i, row = idx >> 2, seg = idx & 3;
            cpa16(sb + 10240u + (uint32_t)(row * 80 + seg * 16), Bg + (size_t)row * CD + seg * 16);
        }
        asm volatile("cp.async.commit_group;" ::: "memory");
    }

    for (int kc = 0; kc < 16; kc++) {
        int buf = kc & 1;
        asm volatile("cp.async.wait_group 0;" ::: "memory");
        __syncthreads();
        if (kc + 1 < 16) {
            int nb = buf ^ 1;
#pragma unroll
            for (int i = 0; i < 2; i++) {
                int idx = tid + 128 * i, row = idx >> 2, seg = idx & 3;
                cpa16(sb + (uint32_t)(nb * 5120 + row * 80 + seg * 16),
                      Ag + (size_t)row * CD + (kc + 1) * 64 + seg * 16);
            }
#pragma unroll
            for (int i = 0; i < 4; i++) {
                int idx = tid + 128 * i, row = idx >> 2, seg = idx & 3;
                cpa16(sb + 10240u + (uint32_t)(nb * 10240 + row * 80 + seg * 16),
                      Bg + (size_t)row * CD + (kc + 1) * 64 + seg * 16);
            }
            asm volatile("cp.async.commit_group;" ::: "memory");
        }
        uint32_t aB = sb + (uint32_t)(buf * 5120);
        uint32_t bB = sb + 10240u + (uint32_t)(buf * 10240);
#pragma unroll
        for (int kk = 0; kk < 2; kk++) {
            uint32_t af[2][4], bfr[4][4];
#pragma unroll
            for (int mi = 0; mi < 2; mi++) {
                uint32_t addr = aB + (uint32_t)((wm * 32 + mi * 16 + (l & 15)) * 80
                                                + kk * 32 + ((l >> 4) << 4));
                ldmx4(af[mi], addr);
            }
#pragma unroll
            for (int np = 0; np < 4; np++) {
                uint32_t addr = bB + (uint32_t)((wn * 64 + np * 16 + (l & 7) + ((l >> 4) << 3)) * 80
                                                + kk * 32 + (((l >> 3) & 1) << 4));
                ldmx4(bfr[np], addr);
            }
#pragma unroll
            for (int mi = 0; mi < 2; mi++)
#pragma unroll
                for (int ni = 0; ni < 8; ni++) {
                    int np = ni >> 1;
                    mma16832f8(acc[mi][ni], af[mi],
                               bfr[np][(ni & 1) * 2], bfr[np][(ni & 1) * 2 + 1]);
                }
        }
    }

    int brow = bx * 64 + wm * 32;
    int bcol = by * 128 + wn * 64;
#pragma unroll
    for (int mi = 0; mi < 2; mi++) {
#pragma unroll
        for (int ni = 0; ni < 8; ni++) {
            int r0 = brow + mi * 16 + (l >> 2);
            int col = bcol + ni * 8 + (l & 3) * 2;
            float c0 = 1.f / (1.f + expf(-acc[mi][ni][0] * INV_WSCALE));
            float c1 = 1.f / (1.f + expf(-acc[mi][ni][1] * INV_WSCALE));
            float c2 = 1.f / (1.f + expf(-acc[mi][ni][2] * INV_WSCALE));
            float c3 = 1.f / (1.f + expf(-acc[mi][ni][3] * INV_WSCALE));
            *(uint16_t*)(out8 + (size_t)r0 * CD + col) = f2e4m3x2(c0, c1);
            *(uint16_t*)(out8 + (size_t)(r0 + 8) * CD + col) = f2e4m3x2(c2, c3);
        }
    }
}

// ------------------- fused GEMM kernel -------------------
// by <  n8by          : e4m3 out into out8qk (stride N2)
// n8by <= by < nby    : bf16 out into outb (stride ostride)
// by >= nby           : fp8 gate path
__global__ void __launch_bounds__(128, 4) gemm_fused(
    const __nv_bfloat16* __restrict__ A, const __nv_bfloat16* __restrict__ Bw,
    __nv_bfloat16* __restrict__ outb, int ostride,
    uint8_t* __restrict__ out8qk, int n8by, int nby,
    const uint8_t* __restrict__ A8, const uint8_t* __restrict__ B8,
    uint8_t* __restrict__ out8gate) {
    extern __shared__ __align__(1024) unsigned char smem[];
    uint32_t sb = s2u(smem);
    if ((int)blockIdx.y >= nby) {
        f8_gate_path(sb, A8, B8, out8gate, blockIdx.x, (int)blockIdx.y - nby);
        return;
    }
    int tid = threadIdx.x;
    int l = tid & 31, w = tid >> 5;
    int wm = w & 1, wn = w >> 1;

    int r0l = tid >> 3, segl = tid & 7;
    const char* ga = (const char*)(A + (size_t)blockIdx.x * 64 * CD) + r0l * 2048 + segl * 16;
    const char* gb = (const char*)(Bw + (size_t)blockIdx.y * 128 * CD) + r0l * 2048 + segl * 16;
    uint32_t so0 = SWZ128((uint32_t)(r0l * 128 + segl * 16));

    float acc[2][8][4];
#pragma unroll
    for (int mi = 0; mi < 2; mi++)
#pragma unroll
        for (int ni = 0; ni < 8; ni++)
#pragma unroll
            for (int j = 0; j < 4; j++) acc[mi][ni][j] = 0.f;

    bf16_mainloop64(sb, ga, gb, so0, wm, wn, l, acc);

    int brow = blockIdx.x * 64 + wm * 32;
    if ((int)blockIdx.y < n8by) {
        int bcol = blockIdx.y * 128 + wn * 64;
#pragma unroll
        for (int mi = 0; mi < 2; mi++) {
#pragma unroll
            for (int ni = 0; ni < 8; ni++) {
                int r0 = brow + mi * 16 + (l >> 2);
                int col = bcol + ni * 8 + (l & 3) * 2;
                *(uint16_t*)(out8qk + (size_t)r0 * N2 + col) =
                    f2e4m3x2(acc[mi][ni][0], acc[mi][ni][1]);
                *(uint16_t*)(out8qk + (size_t)(r0 + 8) * N2 + col) =
                    f2e4m3x2(acc[mi][ni][2], acc[mi][ni][3]);
            }
        }
    } else {
        int bcol = ((int)blockIdx.y - n8by) * 128 + wn * 64;
#pragma unroll
        for (int mi = 0; mi < 2; mi++) {
#pragma unroll
            for (int ni = 0; ni < 8; ni++) {
                int r0 = brow + mi * 16 + (l >> 2);
                int col = bcol + ni * 8 + (l & 3) * 2;
                __nv_bfloat162 p0 = __floats2bfloat162_rn(acc[mi][ni][0], acc[mi][ni][1]);
                __nv_bfloat162 p1 = __floats2bfloat162_rn(acc[mi][ni][2], acc[mi][ni][3]);
                *(__nv_bfloat162*)(outb + (size_t)r0 * ostride + col) = p0;
                *(__nv_bfloat162*)(outb + (size_t)(r0 + 8) * ostride + col) = p1;
            }
        }
    }
}

// ------------------- final bf16 GEMM: out = x + (og@Wo^T)*ls_g -------------------
__global__ void __launch_bounds__(128, 4) gemm_bf16_fin(
    const __nv_bfloat16* __restrict__ A, const __nv_bfloat16* __restrict__ Bw,
    float* __restrict__ outf, const float* __restrict__ evec,
    const float* __restrict__ xres) {
    extern __shared__ __align__(1024) unsigned char smem[];
    uint32_t sb = s2u(smem);
    int tid = threadIdx.x;
    int l = tid & 31, w = tid >> 5;
    int wm = w & 1, wn = w >> 1;

    int r0l = tid >> 3, segl = tid & 7;
    const char* ga = (const char*)(A + (size_t)blockIdx.x * 64 * CD) + r0l * 2048 + segl * 16;
    const char* gb = (const char*)(Bw + (size_t)blockIdx.y * 128 * CD) + r0l * 2048 + segl * 16;
    uint32_t so0 = SWZ128((uint32_t)(r0l * 128 + segl * 16));

    float acc[2][8][4];
#pragma unroll
    for (int mi = 0; mi < 2; mi++)
#pragma unroll
        for (int ni = 0; ni < 8; ni++)
#pragma unroll
            for (int j = 0; j < 4; j++) acc[mi][ni][j] = 0.f;

    bf16_mainloop64(sb, ga, gb, so0, wm, wn, l, acc);

    int brow = blockIdx.x * 64 + wm * 32;
    int bcol = blockIdx.y * 128 + wn * 64;
#pragma unroll
    for (int mi = 0; mi < 2; mi++) {
#pragma unroll
        for (int ni = 0; ni < 8; ni++) {
            int r0 = brow + mi * 16 + (l >> 2);
            int col = bcol + ni * 8 + (l & 3) * 2;
            float e0 = evec[col], e1 = evec[col + 1];
            float2 xv0 = *(const float2*)(xres + (size_t)r0 * CD + col);
            *(float2*)(outf + (size_t)r0 * CD + col) =
                make_float2(xv0.x + acc[mi][ni][0] * e0, xv0.y + acc[mi][ni][1] * e1);
            float2 xv1 = *(const float2*)(xres + (size_t)(r0 + 8) * CD + col);
            *(float2*)(outf + (size_t)(r0 + 8) * CD + col) =
                make_float2(xv1.x + acc[mi][ni][2] * e0, xv1.y + acc[mi][ni][3] * e1);
        }
    }
}

// ------------------- scan kernels -------------------
// QK8: [row][Q|K] e4m3 stride 2048;  EY: [row][E|Y] bf16 stride 2048

// pass 1: RAW chunk sums of k*e + loss. grid (NCH, BN), 1024 thr
__global__ void __launch_bounds__(1024) scan_p1(
    const uint8_t* __restrict__ QK8, const __nv_bfloat16* __restrict__ EY,
    float* __restrict__ cs, float* __restrict__ loss_slot) {
    int b = blockIdx.y, ch = blockIdx.x, c = threadIdx.x;
    size_t base = ((size_t)(b * TNseq + ch * CHL)) * N2 + c;
    float s = 0.f, lsum = 0.f;
#pragma unroll 4
    for (int t = 0; t < CHL; t++) {
        size_t i = base + (size_t)t * N2;
        float k = e4m3_to_f(QK8[i + 1024]);
        float e = __bfloat162float(EY[i]);
        lsum += e * e;
        s += k * e;
    }
    cs[((size_t)b * NCH + ch) * CD + c] = s;
#pragma unroll
    for (int o = 16; o > 0; o >>= 1) lsum += __shfl_xor_sync(0xffffffffu, lsum, o);
    __shared__ float red[32];
    int wid = c >> 5;
    if ((c & 31) == 0) red[wid] = lsum;
    __syncthreads();
    if (c < 32) {
        float v2 = red[c];
#pragma unroll
        for (int o = 16; o > 0; o >>= 1) v2 += __shfl_xor_sync(0xffffffffu, v2, o);
        if (c == 0) atomicAdd(loss_slot, v2 * (1.f / 16777216.f));
    }
}

// pass 2: per-block exclusive prefix of raw chunk sums, then replay chunk -> og.
__global__ void __launch_bounds__(1024) scan_p3(
    const uint8_t* __restrict__ QK8, const __nv_bfloat16* __restrict__ EY,
    const uint8_t* __restrict__ Gt8, const float* __restrict__ cs,
    __nv_bfloat16* __restrict__ ogb) {
    __shared__ float ps_s[CHL];
    int b = blockIdx.y, ch = blockIdx.x, c = threadIdx.x;
    if (c < CHL) {
        int gt = ch * CHL + c;
        ps_s[c] = 1.f / (1.f + 0.1f * logf((float)(gt + 1)));
    }
    __syncthreads();
    float run = 0.f;
    for (int j = 0; j < ch; j++) run += cs[((size_t)b * NCH + j) * CD + c];
    size_t base2 = ((size_t)(b * TNseq + ch * CHL)) * N2 + c;
    size_t base1 = ((size_t)(b * TNseq + ch * CHL)) * CD + c;
#pragma unroll 4
    for (int t = 0; t < CHL; t++) {
        size_t i2 = base2 + (size_t)t * N2;
        size_t i1 = base1 + (size_t)t * CD;
        float q = e4m3_to_f(QK8[i2]);
        float k = e4m3_to_f(QK8[i2 + 1024]);
        float e = __bfloat162float(EY[i2]);
        float y = __bfloat162float(EY[i2 + 1024]);
        float g = e4m3_to_f(Gt8[i1]);
        float op = (y - q * run * ps_s[t]) * g;
        ogb[i1] = __float2bfloat16(op);
        run += k * e;
    }
}

// ------------------- launch -------------------
extern "C" void kernel_launch(void* const* d_in, const int* in_sizes, int n_in,
                              void* d_out, int out_size) {
    const float* x     = (const float*)d_in[0];
    const float* W0    = (const float*)d_in[1];
    const float* Ai    = (const float*)d_in[2];
    const float* Bi    = (const float*)d_in[3];
    const float* loglr = (const float*)d_in[4];
    const float* Wq    = (const float*)d_in[5];
    const float* Wk    = (const float*)d_in[6];
    const float* Wv    = (const float*)d_in[7];
    const float* Wo    = (const float*)d_in[8];
    const float* Wg    = (const float*)d_in[9];
    const float* lng   = (const float*)d_in[10];
    const float* lnb   = (const float*)d_in[11];
    const float* lsg   = (const float*)d_in[12];
    float* out = (float*)d_out;
    float* loss_slot = out + (out_size - 1);

    unsigned char* sc = nullptr;
    cudaGetSymbolAddress((void**)&sc, g_scratch);

    uint8_t*       QK8  = (uint8_t*)(sc + OFF_QK8);
    __nv_bfloat16* EY   = (__nv_bfloat16*)(sc + OFF_EY);
    __nv_bfloat16* Hb   = (__nv_bfloat16*)(sc + OFF_H);
    uint8_t*       X8   = (uint8_t*)(sc + OFF_X8);
    uint8_t*       G8   = (uint8_t*)(sc + OFF_G8);
    __nv_bfloat16* OGb  = (__nv_bfloat16*)(sc + OFF_OGB);
    __nv_bfloat16* Wcat = (__nv_bfloat16*)(sc + OFF_WCAT);
    __nv_bfloat16* WkT  = (__nv_bfloat16*)(sc + OFF_WKT);
    __nv_bfloat16* W0T  = (__nv_bfloat16*)(sc + OFF_W0T);
    uint8_t*       Wg8  = (uint8_t*)(sc + OFF_WG8);
    __nv_bfloat16* WoB  = (__nv_bfloat16*)(sc + OFF_WOB);
    float* cs = (float*)(sc + OFF_CS);

    cudaFuncSetAttribute(gemm_fused, cudaFuncAttributeMaxDynamicSharedMemorySize, GF_SMEM);
    cudaFuncSetAttribute(gemm_bf16_fin, cudaFuncAttributeMaxDynamicSharedMemorySize, GF_SMEM);

    // 1: all weight prep
    wprep_all<<<dim3(1024, 7), 256>>>(Wq, Wk, Wv, Wg, Wo, W0, Ai, Bi, loglr,
                                      Wcat, Wg8, WoB, WkT, W0T);
    // 2: y0 combined weight: Wcat[3072+d][c] = sum_e W0T[d][e]*WkT[c][e] (bf16 path only)
    gemm_fused<<<dim3(16, 8), 128, GF_SMEM>>>(W0T, WkT, Wcat + (size_t)3072 * CD, CD,
                                              nullptr, 0, 8, nullptr, nullptr, nullptr);
    // 3: layernorm (h bf16, x e4m3) + WE = Wy0 - Wv + loss zero
    ln_prep<<<MR + 1024, 256>>>(x, lng, lnb, Hb, X8, Wcat, loss_slot);
    // 4: fused GEMM: by<16 -> Q|K e4m3 ; 16<=by<32 -> E|Y bf16 ; by>=32 -> gate fp8
    gemm_fused<<<dim3(MR / 64, 40), 128, GF_SMEM>>>(
        Hb, Wcat, EY, N2, QK8, 16, 32, X8, Wg8, G8);
    // 5: raw chunk sums + loss
    scan_p1<<<dim3(NCH, BN), 1024>>>(QK8, EY, cs, loss_slot);
    // 6: prefix + replay -> og
    scan_p3<<<dim3(NCH, BN), 1024>>>(QK8, EY, G8, cs, OGb);
    // 7: out = x + (og @ Wo^T) * ls_g
    gemm_bf16_fin<<<dim3(MR / 64, CD / 128), 128, GF_SMEM>>>(OGb, WoB, out, lsg, x);
}